// round 17
// baseline (speedup 1.0000x reference)
#include <cuda_runtime.h>
#include <cuda_fp16.h>
#include <cstdint>

#define N_NODES 50000
#define E_MAX   800000
#define D_IN 128
#define D_H 96
#define D_OUT 32

#define SCAN_B 256
#define NBLK ((N_NODES + SCAN_B - 1) / SCAN_B)   // 196

// ---------------------------------------------------------------------------
// Scratch (__device__ globals; allocation-free rule)
// g_deg invariant: ZERO at entry of every launch (zero-init at load; fill's
// atomicSub returns it to zero each launch).
// ---------------------------------------------------------------------------
__device__ __half g_h1h[N_NODES * D_H];     // x @ W1, fp16
__device__ __half g_h2h[N_NODES * D_OUT];   // relu(A@h1) @ W2, fp16
__device__ int    g_deg[N_NODES];           // degree counts / fill cursor
__device__ int    g_start[N_NODES + 1];     // CSR row starts (by dst)
__device__ int    g_excl[N_NODES];          // block-local exclusive prescan
__device__ int    g_bsum[NBLK];             // per-block sums
__device__ int2   g_pair[E_MAX];            // per-edge {src, val_bits}

// ---------------------------------------------------------------------------
// GEMM1 via HMMA (mma.sync.m16n8k16, plain compute_100 PTX):
// per block (256 thr, 8 warps): h1[128 rows][96 cols], K=128, fp32 accum.
// ---------------------------------------------------------------------------
#define G1_APITCH 136
#define G1_SA_ELEMS (128 * G1_APITCH)
#define G1_SMEM ((G1_SA_ELEMS + D_H * G1_APITCH) * sizeof(__half))  // ~60.9 KB

__global__ void __launch_bounds__(256)
gemm1_hmma_kernel(const float* __restrict__ x, const float* __restrict__ W1) {
    extern __shared__ __half smh[];
    __half* sA = smh;                    // [128][136]
    __half* sB = smh + G1_SA_ELEMS;      // [96][136]

    int tid = threadIdx.x, wid = tid >> 5, lane = tid & 31;
    int rowBase = blockIdx.x * 128;

    for (int ch = tid; ch < 2048; ch += 256) {
        int row = ch >> 4;
        int col0 = (ch & 15) * 8;
        int grow = rowBase + row;
        float4 f0, f1;
        if (grow < N_NODES) {
            const float4* xp = (const float4*)(x + (long)grow * D_IN + col0);
            f0 = xp[0]; f1 = xp[1];
        } else {
            f0 = make_float4(0.f, 0.f, 0.f, 0.f); f1 = f0;
        }
        __half2 h0 = __floats2half2_rn(f0.x, f0.y);
        __half2 h1 = __floats2half2_rn(f0.z, f0.w);
        __half2 h2 = __floats2half2_rn(f1.x, f1.y);
        __half2 h3 = __floats2half2_rn(f1.z, f1.w);
        uint4 v;
        v.x = *(uint32_t*)&h0; v.y = *(uint32_t*)&h1;
        v.z = *(uint32_t*)&h2; v.w = *(uint32_t*)&h3;
        *(uint4*)(sA + row * G1_APITCH + col0) = v;
    }

    for (int i = tid; i < D_IN * D_H; i += 256) {
        int k = i / D_H, c = i - k * D_H;
        sB[c * G1_APITCH + k] = __float2half_rn(W1[i]);
    }
    __syncthreads();

    int g  = lane >> 2;
    int tq = (lane & 3) * 2;
    int warpRow = wid * 16;

    float c[12][4];
#pragma unroll
    for (int nt = 0; nt < 12; nt++) {
        c[nt][0] = 0.f; c[nt][1] = 0.f; c[nt][2] = 0.f; c[nt][3] = 0.f;
    }

    const __half* arow0 = sA + (warpRow + g) * G1_APITCH + tq;
    const __half* arow1 = arow0 + 8 * G1_APITCH;

#pragma unroll
    for (int ks = 0; ks < 8; ks++) {
        int k0 = ks * 16;
        uint32_t a0 = *(const uint32_t*)(arow0 + k0);
        uint32_t a1 = *(const uint32_t*)(arow1 + k0);
        uint32_t a2 = *(const uint32_t*)(arow0 + k0 + 8);
        uint32_t a3 = *(const uint32_t*)(arow1 + k0 + 8);
#pragma unroll
        for (int nt = 0; nt < 12; nt++) {
            const __half* brow = sB + (nt * 8 + g) * G1_APITCH + tq + k0;
            uint32_t b0 = *(const uint32_t*)(brow);
            uint32_t b1 = *(const uint32_t*)(brow + 8);
            asm volatile(
                "mma.sync.aligned.m16n8k16.row.col.f32.f16.f16.f32 "
                "{%0,%1,%2,%3}, {%4,%5,%6,%7}, {%8,%9}, {%0,%1,%2,%3};"
                : "+f"(c[nt][0]), "+f"(c[nt][1]), "+f"(c[nt][2]), "+f"(c[nt][3])
                : "r"(a0), "r"(a1), "r"(a2), "r"(a3), "r"(b0), "r"(b1));
        }
    }

    int r0 = rowBase + warpRow + g;
    int r1 = r0 + 8;
#pragma unroll
    for (int nt = 0; nt < 12; nt++) {
        int col = nt * 8 + tq;
        if (r0 < N_NODES)
            *(__half2*)(g_h1h + (long)r0 * D_H + col) = __floats2half2_rn(c[nt][0], c[nt][1]);
        if (r1 < N_NODES)
            *(__half2*)(g_h1h + (long)r1 * D_H + col) = __floats2half2_rn(c[nt][2], c[nt][3]);
    }
}

// ---------------------------------------------------------------------------
// CSR build: count -> block_scan -> finalize(w/ inline bsum reduce) -> fill
// ---------------------------------------------------------------------------
__global__ void count_kernel(const int* __restrict__ dst, int n_edges) {
    int e = blockIdx.x * blockDim.x + threadIdx.x;
    if (e < n_edges) atomicAdd(&g_deg[dst[e]], 1);
}

__global__ void block_scan_kernel() {
    __shared__ int ws[8];
    int i = blockIdx.x * SCAN_B + threadIdx.x;
    int v = (i < N_NODES) ? g_deg[i] : 0;
    int lane = threadIdx.x & 31, wid = threadIdx.x >> 5;

    int inc = v;
#pragma unroll
    for (int off = 1; off < 32; off <<= 1) {
        int n = __shfl_up_sync(0xffffffffu, inc, off);
        if (lane >= off) inc += n;
    }
    if (lane == 31) ws[wid] = inc;
    __syncthreads();
    if (wid == 0) {
        int s = (lane < 8) ? ws[lane] : 0;
#pragma unroll
        for (int off = 1; off < 8; off <<= 1) {
            int n = __shfl_up_sync(0xffffffffu, s, off);
            if (lane >= off) s += n;
        }
        if (lane < 8) ws[lane] = s;
    }
    __syncthreads();

    int woff = (wid == 0) ? 0 : ws[wid - 1];
    if (i < N_NODES) g_excl[i] = woff + inc - v;
    if (threadIdx.x == SCAN_B - 1) g_bsum[blockIdx.x] = ws[7];
}

__global__ void finalize_start_kernel(int n_edges) {
    __shared__ int sp[SCAN_B];
    int bid = blockIdx.x;
    int t = threadIdx.x;

    sp[t] = (t < bid && t < NBLK) ? g_bsum[t] : 0;
    __syncthreads();
#pragma unroll
    for (int off = SCAN_B / 2; off > 0; off >>= 1) {
        if (t < off) sp[t] += sp[t + off];
        __syncthreads();
    }
    int boff = sp[0];

    int i = bid * SCAN_B + t;
    if (i < N_NODES) g_start[i] = g_excl[i] + boff;
    if (i == 0) g_start[N_NODES] = n_edges;
}

__global__ void fill_kernel(const int* __restrict__ src,
                            const int* __restrict__ dst,
                            const float* __restrict__ val,
                            int n_edges) {
    int e = blockIdx.x * blockDim.x + threadIdx.x;
    if (e >= n_edges) return;
    int d = dst[e];
    int pos = g_start[d] + atomicSub(&g_deg[d], 1) - 1;
    g_pair[pos] = make_int2(src[e], __float_as_int(val[e]));
}

// ---------------------------------------------------------------------------
// Fused layer 1 aggregation + relu + GEMM2 (fp16 h1 gathers, fp32 accum).
// 8-edge unroll: 8 pair loads then 8 independent gathers in flight.
// ---------------------------------------------------------------------------
#define FW_WARPS 32
#define SROW_PAD 100

__device__ __forceinline__ void f16x4_fma(uint2 raw, float v,
                                          float& ax, float& ay,
                                          float& az, float& aw) {
    float2 f0 = __half22float2(*reinterpret_cast<const __half2*>(&raw.x));
    float2 f1 = __half22float2(*reinterpret_cast<const __half2*>(&raw.y));
    ax = fmaf(v, f0.x, ax); ay = fmaf(v, f0.y, ay);
    az = fmaf(v, f1.x, az); aw = fmaf(v, f1.y, aw);
}

__global__ void __launch_bounds__(FW_WARPS * 32)
fused_agg_gemm2_kernel(const float* __restrict__ W2) {
    __shared__ float sW2[D_H * D_OUT];
    __shared__ float srow[FW_WARPS][SROW_PAD];

    int t = threadIdx.x;
    for (int i = t; i < D_H * D_OUT; i += blockDim.x) sW2[i] = W2[i];
    __syncthreads();

    int w    = t >> 5;
    int lane = t & 31;
    int n    = blockIdx.x * FW_WARPS + w;
    if (n >= N_NODES) return;

    const int2* __restrict__ pp = g_pair;
    int pBeg = g_start[n];
    int pEnd = g_start[n + 1];

    float ax = 0.f, ay = 0.f, az = 0.f, aw = 0.f;
    if (lane < 24) {
        int p = pBeg;
        for (; p + 7 < pEnd; p += 8) {
            int2 pr[8];
#pragma unroll
            for (int j = 0; j < 8; j++) pr[j] = pp[p + j];
            uint2 r[8];
#pragma unroll
            for (int j = 0; j < 8; j++)
                r[j] = *reinterpret_cast<const uint2*>(
                    g_h1h + (long)pr[j].x * D_H + lane * 4);
#pragma unroll
            for (int j = 0; j < 8; j++)
                f16x4_fma(r[j], __int_as_float(pr[j].y), ax, ay, az, aw);
        }
        if (p + 3 < pEnd) {
            int2 pr[4];
#pragma unroll
            for (int j = 0; j < 4; j++) pr[j] = pp[p + j];
            uint2 r[4];
#pragma unroll
            for (int j = 0; j < 4; j++)
                r[j] = *reinterpret_cast<const uint2*>(
                    g_h1h + (long)pr[j].x * D_H + lane * 4);
#pragma unroll
            for (int j = 0; j < 4; j++)
                f16x4_fma(r[j], __int_as_float(pr[j].y), ax, ay, az, aw);
            p += 4;
        }
        for (; p < pEnd; p++) {
            int2 pr = pp[p];
            uint2 r = *reinterpret_cast<const uint2*>(
                g_h1h + (long)pr.x * D_H + lane * 4);
            f16x4_fma(r, __int_as_float(pr.y), ax, ay, az, aw);
        }
        float4 r = make_float4(fmaxf(ax, 0.f), fmaxf(ay, 0.f),
                               fmaxf(az, 0.f), fmaxf(aw, 0.f));
        *reinterpret_cast<float4*>(&srow[w][lane * 4]) = r;
    }
    __syncwarp();

    float acc = 0.f;
    const float4* sr4 = reinterpret_cast<const float4*>(&srow[w][0]);
#pragma unroll
    for (int k4 = 0; k4 < D_H / 4; k4++) {
        float4 s = sr4[k4];
        int k = k4 * 4;
        acc = fmaf(s.x, sW2[(k + 0) * D_OUT + lane], acc);
        acc = fmaf(s.y, sW2[(k + 1) * D_OUT + lane], acc);
        acc = fmaf(s.z, sW2[(k + 2) * D_OUT + lane], acc);
        acc = fmaf(s.w, sW2[(k + 3) * D_OUT + lane], acc);
    }
    g_h2h[(long)n * D_OUT + lane] = __float2half_rn(acc);
}

// ---------------------------------------------------------------------------
// Layer 2 aggregation (gather), fp16 h2, fp32 accum, 8-edge unroll.
// ---------------------------------------------------------------------------
__global__ void __launch_bounds__(FW_WARPS * 32)
spmm2_gather_kernel(float* __restrict__ out) {
    int t    = threadIdx.x;
    int w    = t >> 5;
    int lane = t & 31;
    int n    = blockIdx.x * FW_WARPS + w;
    if (n >= N_NODES) return;

    const int2* __restrict__ pp = g_pair;
    int pBeg = g_start[n];
    int pEnd = g_start[n + 1];

    float acc = 0.f;
    int p = pBeg;
    for (; p + 7 < pEnd; p += 8) {
        int2 pr[8];
#pragma unroll
        for (int j = 0; j < 8; j++) pr[j] = pp[p + j];
        float h[8];
#pragma unroll
        for (int j = 0; j < 8; j++)
            h[j] = __half2float(g_h2h[(long)pr[j].x * D_OUT + lane]);
#pragma unroll
        for (int j = 0; j < 8; j++)
            acc = fmaf(__int_as_float(pr[j].y), h[j], acc);
    }
    if (p + 3 < pEnd) {
        int2 pr[4];
#pragma unroll
        for (int j = 0; j < 4; j++) pr[j] = pp[p + j];
        float h[4];
#pragma unroll
        for (int j = 0; j < 4; j++)
            h[j] = __half2float(g_h2h[(long)pr[j].x * D_OUT + lane]);
#pragma unroll
        for (int j = 0; j < 4; j++)
            acc = fmaf(__int_as_float(pr[j].y), h[j], acc);
        p += 4;
    }
    for (; p < pEnd; p++) {
        int2 pr = pp[p];
        acc = fmaf(__int_as_float(pr.y),
                   __half2float(g_h2h[(long)pr.x * D_OUT + lane]), acc);
    }
    out[(long)n * D_OUT + lane] = acc;
}

// ---------------------------------------------------------------------------
// Launch: count -> gemm1_hmma -> block_scan -> finalize -> fill -> fused -> spmm2
// ---------------------------------------------------------------------------
extern "C" void kernel_launch(void* const* d_in, const int* in_sizes, int n_in,
                              void* d_out, int out_size) {
    const float* x        = (const float*)d_in[0];
    const int*   edge_src = (const int*)  d_in[1];
    const int*   edge_dst = (const int*)  d_in[2];
    const float* edge_val = (const float*)d_in[3];
    const float* W1       = (const float*)d_in[4];
    const float* W2       = (const float*)d_in[5];
    float*       out      = (float*)d_out;

    int E = in_sizes[1];

    static bool s_init = false;
    if (!s_init) {
        cudaFuncSetAttribute(gemm1_hmma_kernel,
                             cudaFuncAttributeMaxDynamicSharedMemorySize,
                             (int)G1_SMEM);
        s_init = true;
    }

    count_kernel<<<(E + 255) / 256, 256>>>(edge_dst, E);

    int g1_grid = (N_NODES + 127) / 128;   // 391
    gemm1_hmma_kernel<<<g1_grid, 256, G1_SMEM>>>(x, W1);

    block_scan_kernel<<<NBLK, SCAN_B>>>();
    finalize_start_kernel<<<NBLK, SCAN_B>>>(E);
    fill_kernel<<<(E + 255) / 256, 256>>>(edge_src, edge_dst, edge_val, E);

    int fw_grid = (N_NODES + FW_WARPS - 1) / FW_WARPS;
    fused_agg_gemm2_kernel<<<fw_grid, FW_WARPS * 32>>>(W2);

    spmm2_gather_kernel<<<fw_grid, FW_WARPS * 32>>>(out);
}